// round 11
// baseline (speedup 1.0000x reference)
#include <cuda_runtime.h>
#include <cuda_bf16.h>

// ConvSSM scan, spatial domain.
//   Phase 1: U_t = B (*) x_t for all (t,b,c)  — parallel, scan-layout scratch.
//   Phase 2: h_t = A (*) h_{t-1} + U_t        — 64 sequential steps, one CTA
//            per (b,c). h in registers (warp w: rows 4w..4w+3, lane l: cols
//            2l,2l+1). Horizontal wrap via u64 shfl; vertical halo via packed
//            double-buffered SMEM. Ring sync: 16 pairwise named barriers
//            (warp w <-> w+1) instead of a global __syncthreads -> warps drift,
//            LSU bursts spread, no 16-warp convoy.
// (*) = circular conv on the 64x64 torus (== reference zero-padded FFT product).

#define NT 64
#define NB 2
#define NC 32
#define NH 32
#define NW 32
#define NBC 64              // NB*NC chains
#define USLOTS 153          // 17*9  (l=0..16 col pair, w=0..8 warp)
#define USLICE (USLOTS * 8) // floats per (t,bc) slice

// +1 guard slice for unconditional distance-1 prefetch.
__device__ __align__(16) float g_U[(size_t)(NT + 1) * NBC * USLICE];

typedef unsigned long long u64;

__device__ __forceinline__ u64 pk(float lo, float hi) {
    u64 r; asm("mov.b64 %0, {%1, %2};" : "=l"(r) : "f"(lo), "f"(hi)); return r;
}
__device__ __forceinline__ float2 unpk(u64 v) {
    float2 f; asm("mov.b64 {%0, %1}, %2;" : "=f"(f.x), "=f"(f.y) : "l"(v)); return f;
}
__device__ __forceinline__ u64 f2fma(u64 a, u64 b, u64 c) {
    u64 d; asm("fma.rn.f32x2 %0, %1, %2, %3;" : "=l"(d) : "l"(a), "l"(b), "l"(c));
    return d;
}
__device__ __forceinline__ void barpair(int id) {
    asm volatile("bar.sync %0, 64;" :: "r"(id) : "memory");
}

// Operands for one input row from packed pair P (cols 2l,2l+1):
//   O0 = {x, x+1} = P ;  O2 = {x-2, x-1} = left-neighbor pair (u64 shfl) ;
//   O1 = {x-1, x}  (one pack).
__device__ __forceinline__ void mkops(u64 P, int src, u64& O0, u64& O1, u64& O2) {
    u64 L = __shfl_sync(0xffffffffu, P, src);
    float2 Pf = unpk(P), Lf = unpk(L);
    O0 = P; O2 = L; O1 = pk(Lf.y, Pf.x);
}
__device__ __forceinline__ u64 cdy(const u64* A2, int dy, u64 O0, u64 O1, u64 O2, u64 acc) {
    acc = f2fma(A2[3 * dy + 0], O0, acc);
    acc = f2fma(A2[3 * dy + 1], O1, acc);
    acc = f2fma(A2[3 * dy + 2], O2, acc);
    return acc;
}

// ---------------------------------------------------------------------------
// Phase 1: U = B (*) x (zero-padded x), one CTA per (t,b,c) slice.
// 192 threads; threads 0..152 compute the 8 floats scan-thread (l,w) reads.
// ---------------------------------------------------------------------------
__global__ __launch_bounds__(192)
void u_precompute(const float* __restrict__ x, const float* __restrict__ Bk)
{
    __shared__ __align__(16) float xs[38 * 44];   // idx = actual + 2, zero border
    const int n   = blockIdx.x;           // n = t*NBC + bc
    const int c   = n & (NC - 1);
    const int tid = threadIdx.x;

    for (int i = tid; i < 38 * 44; i += 192) xs[i] = 0.0f;
    __syncthreads();

    const float2* xsl = (const float2*)(x + (size_t)n * (NH * NW));
    for (int i = tid; i < (NH * NW) / 2; i += 192) {
        const int r = i >> 4, c2 = (i & 15) * 2;
        float2 v = xsl[i];
        *(float2*)&xs[(r + 2) * 44 + c2 + 2] = v;
    }

    float Bw[9];
#pragma unroll
    for (int j = 0; j < 9; ++j) Bw[j] = Bk[c * 9 + j];
    __syncthreads();

    if (tid < USLOTS) {
        const int l = tid / 9;            // col pair 0..16 -> cols 2l,2l+1
        const int w = tid % 9;            // row group -> rows 4w..4w+3
        const int c0 = 2 * l;
        float o[4][2];
#pragma unroll
        for (int i = 0; i < 4; ++i) {
            const int r = 4 * w + i;      // rows 34,35 compute to 0 naturally
            o[i][0] = 0.f; o[i][1] = 0.f;
#pragma unroll
            for (int dy = 0; dy < 3; ++dy) {
                const float* rp = &xs[(r + 2 - dy) * 44 + c0 + 2];
#pragma unroll
                for (int dx = 0; dx < 3; ++dx) {
                    o[i][0] = fmaf(Bw[dy * 3 + dx], rp[-dx], o[i][0]);
                    o[i][1] = fmaf(Bw[dy * 3 + dx], rp[1 - dx], o[i][1]);
                }
            }
        }
        float* up = &g_U[(size_t)n * USLICE + tid * 8];
        *(float4*)(up)     = make_float4(o[0][0], o[0][1], o[1][0], o[1][1]);
        *(float4*)(up + 4) = make_float4(o[2][0], o[2][1], o[3][0], o[3][1]);
    }
}

// ---------------------------------------------------------------------------
// Phase 2: register-resident scan. 512 threads = 16 warps per CTA, 1 CTA/(b,c).
// Ring sync: barrier id w joins warps (w, w+1 mod 16), count 64.
//   even warps: down-barrier (B_w) first;  odd warps: up-barrier (B_{w-1}) first.
// ---------------------------------------------------------------------------
__global__ __launch_bounds__(512, 1)
void convssm_scan(const float* __restrict__ Ak, float* __restrict__ out)
{
    // halo[buf][w][lane] = {row 4w+2 pair, row 4w+3 pair} (16 B)
    __shared__ __align__(16) ulonglong2 halo[2][16][32];

    const int tid  = threadIdx.x;
    const int lane = tid & 31;
    const int w    = tid >> 5;
    const int bc   = blockIdx.x;
    const int c    = bc & (NC - 1);
    const int src  = (lane + 31) & 31;     // circular left neighbor
    const int wm1  = (w + 15) & 15;        // warp above (producer of our halo)
    const bool evenw = (w & 1) == 0;

    u64 A2[9];
#pragma unroll
    for (int j = 0; j < 9; ++j) { float a = Ak[c * 9 + j]; A2[j] = pk(a, a); }

    // h_{-1} = 0 (packed state)
    u64 h0 = 0ull, h1 = 0ull, h2 = 0ull, h3 = 0ull;

    for (int i = tid; i < 2 * 16 * 32; i += 512)
        ((ulonglong2*)halo)[i] = make_ulonglong2(0ull, 0ull);

    // U stream (scan layout): slot (lane, w), 8 floats.
    const bool ul   = (lane < 17) && (w < 9);
    const float* up = g_U + (size_t)bc * USLICE + (lane * 9 + w) * 8;
    const size_t ustep = (size_t)NBC * USLICE;

    // Prefetch U_0.
    u64 ua0, ua1, ua2, ua3;
    {
        float4 a = make_float4(0.f,0.f,0.f,0.f), b = a;
        if (ul) { a = *(const float4*)(up); b = *(const float4*)(up + 4); }
        ua0 = pk(a.x, a.y); ua1 = pk(a.z, a.w);
        ua2 = pk(b.x, b.y); ua3 = pk(b.z, b.w);
    }
    up += ustep;

    float* ob = out + (size_t)bc * (NH * NW) + (4 * w) * NW + 2 * lane;
    const bool emits = (w < 8) && (lane < 16);

    __syncthreads();   // halo zero-init visible to all (uses bar 0 full-count once)

#pragma unroll 2
    for (int t = 0; t < NT; ++t) {
        const int pb = t & 1;

        // Vertical halo rows (h_{t-1} rows 4w-2, 4w-1), one LDS.128.
        // Ready since up-barrier of step t-1; producer overwrites only after
        // our up-barrier of step t (below) -> read now, before arriving.
        ulonglong2 hv = halo[pb][wm1][lane];

        // acc = U_t
        u64 acc0 = ua0, acc1 = ua1, acc2 = ua2, acc3 = ua3;

        // Prefetch U_{t+1} (guard slice at t = NT-1).
        float4 na = make_float4(0.f,0.f,0.f,0.f), nb = na;
        if (ul) { na = *(const float4*)(up); nb = *(const float4*)(up + 4); }
        up += ustep;

        // acc += A (*) h_{t-1}
        u64 O0, O1, O2;
        mkops(hv.x, src, O0, O1, O2);   // input row -2
        acc0 = cdy(A2, 2, O0, O1, O2, acc0);
        mkops(hv.y, src, O0, O1, O2);   // input row -1
        acc0 = cdy(A2, 1, O0, O1, O2, acc0);
        acc1 = cdy(A2, 2, O0, O1, O2, acc1);
        mkops(h0, src, O0, O1, O2);     // input row 0
        acc0 = cdy(A2, 0, O0, O1, O2, acc0);
        acc1 = cdy(A2, 1, O0, O1, O2, acc1);
        acc2 = cdy(A2, 2, O0, O1, O2, acc2);
        mkops(h1, src, O0, O1, O2);     // input row 1
        acc1 = cdy(A2, 0, O0, O1, O2, acc1);
        acc2 = cdy(A2, 1, O0, O1, O2, acc2);
        acc3 = cdy(A2, 2, O0, O1, O2, acc3);
        mkops(h2, src, O0, O1, O2);     // input row 2
        acc2 = cdy(A2, 0, O0, O1, O2, acc2);
        acc3 = cdy(A2, 1, O0, O1, O2, acc3);
        mkops(h3, src, O0, O1, O2);     // input row 3
        acc3 = cdy(A2, 0, O0, O1, O2, acc3);

        h0 = acc0; h1 = acc1; h2 = acc2; h3 = acc3;

        // Publish bottom-2 rows for warp w+1 (one STS.128) into buffer pb^1.
        // Safe: w+1 consumed this buffer at step t-1 (down-barrier of t-1).
        halo[pb ^ 1][w][lane] = make_ulonglong2(acc2, acc3);

        // Emit cropped 32x32 output.
        if (emits) {
            float* o = ob + (size_t)t * (NBC * NH * NW);
            *(u64*)(o)          = acc0;
            *(u64*)(o + NW)     = acc1;
            *(u64*)(o + 2 * NW) = acc2;
            *(u64*)(o + 3 * NW) = acc3;
        }

        // Commit U_{t+1}.
        ua0 = pk(na.x, na.y); ua1 = pk(na.z, na.w);
        ua2 = pk(nb.x, nb.y); ua3 = pk(nb.z, nb.w);

        // Ring sync (deadlock-free even/odd ordering).
        if (evenw) { barpair(w); barpair(wm1); }
        else       { barpair(wm1); barpair(w); }
    }
}

extern "C" void kernel_launch(void* const* d_in, const int* in_sizes, int n_in,
                              void* d_out, int out_size) {
    const float* x  = (const float*)d_in[0];
    const float* Ak = (const float*)d_in[1];
    const float* Bk = (const float*)d_in[2];
    float* out = (float*)d_out;
    u_precompute<<<NT * NBC, 192>>>(x, Bk);
    convssm_scan<<<NBC, 512>>>(Ak, out);
}